// round 13
// baseline (speedup 1.0000x reference)
#include <cuda_runtime.h>
#include <math.h>

#define W_IMG 512
#define H_IMG 512
#define MAX_N (32 * W_IMG * H_IMG)
#define MAX_WORDS (MAX_N / 64)
#define MAX_NODES (MAX_WORDS * 32)   // <=32 runs per 64-px word
#define SENT 0x7F7F7F7F              // memset-able "I am root" sentinel

// Run-indexed node arrays (L2-resident).
__device__ int   g_lab[MAX_NODES];   // SENT = root; else parent/root id (< own id)
__device__ int   g_ar[MAX_NODES];    // area at roots (memset 0, atomicAdd)
__device__ float g_rsum[MAX_NODES];  // per-run sum of (b - x); plain stores
__device__ unsigned long long g_bits[MAX_WORDS];
// 0 = sum_fg bce/(w+1), 2 = sum_fg w, 3 = N_fg, 4 = sum_all b, 5 = sum_fg b
__device__ double g_acc[6];

// ---------------------------------------------------------------------------
__device__ __forceinline__ int find_root(int x) {
    int p = g_lab[x];
    while (p < x) { x = p; p = g_lab[x]; }   // SENT > x  ->  x is root
    return x;
}

__device__ __forceinline__ void merge(int a, int b) {
    while (true) {
        a = find_root(a);
        b = find_root(b);
        if (a == b) return;
        if (a < b) { int t = a; a = b; b = t; }   // a = hi, b = lo
        int old = atomicMin(&g_lab[a], b);
        if (old >= a) return;   // old==SENT: a was root, now linked
        a = old;                // lost race; keep merging the previous parent
    }
}

// node id of the run CONTAINING set bit k of word w with starts mask st
__device__ __forceinline__ int node_of(int w, unsigned long long st, int k) {
    return (w << 5) + __popcll(st & ((2ull << k) - 1ull)) - 1;
}

__device__ __forceinline__ int run_len(unsigned long long m, int k) {
    unsigned long long inv = ~(m >> k);
    return inv ? (__ffsll((long long)inv) - 1) : (64 - k);
}

__device__ __forceinline__ double warp_sum(double v) {
#pragma unroll
    for (int off = 16; off > 0; off >>= 1)
        v += __shfl_down_sync(0xFFFFFFFFu, v, off);
    return v;
}

// ---------------------------------------------------------------------------
// k_prep: thread per quad; build word mask via shfl. NO node writes.
// ---------------------------------------------------------------------------
__global__ void k_prep(const float* __restrict__ tgt, int nquad) {
    int t = blockIdx.x * blockDim.x + threadIdx.x;
    if (t < nquad) {
        int w = t >> 4;
        int b0 = (t & 15) << 2;
        float4 v = __ldg(&((const float4*)tgt)[t]);
        unsigned long long nib = 0ull;
        if (v.x > 0.f) nib |= 1ull;
        if (v.y > 0.f) nib |= 2ull;
        if (v.z > 0.f) nib |= 4ull;
        if (v.w > 0.f) nib |= 8ull;
        unsigned long long m = nib << b0;
        m |= __shfl_xor_sync(0xFFFFFFFFu, m, 1);
        m |= __shfl_xor_sync(0xFFFFFFFFu, m, 2);
        m |= __shfl_xor_sync(0xFFFFFFFFu, m, 4);
        m |= __shfl_xor_sync(0xFFFFFFFFu, m, 8);
        if ((t & 15) == 0) g_bits[w] = m;
    }
    if (blockIdx.x == 0 && threadIdx.x < 6) g_acc[threadIdx.x] = 0.0;
}

// ---------------------------------------------------------------------------
// k_union: word-level bitmask merges (run-indexed node ids)
// ---------------------------------------------------------------------------
__global__ void k_union(int nwords) {
    int w = blockIdx.x * blockDim.x + threadIdx.x;
    if (w >= nwords) return;
    unsigned long long cur = g_bits[w];
    if (!cur) return;
    unsigned long long stc = cur & ~(cur << 1);
    int wx = w & 7;
    int wy = (w >> 3) & (H_IMG - 1);

    if (wx && (cur & 1ull)) {
        unsigned long long L = g_bits[w - 1];
        if (L >> 63) {
            unsigned long long stl = L & ~(L << 1);
            merge((w << 5), ((w - 1) << 5) + __popcll(stl) - 1);
        }
    }
    if (wy) {
        unsigned long long up = g_bits[w - 8];
        unsigned long long ov = cur & up;
        if (ov) {
            unsigned long long stu = up & ~(up << 1);
            unsigned long long need = ov & ~(ov << 1);
            while (need) {
                int k = __ffsll((long long)need) - 1;
                need &= need - 1;
                merge(node_of(w, stc, k), node_of(w - 8, stu, k));
            }
        }
    }
}

// ---------------------------------------------------------------------------
// k_area: thread per quad; run starts in my 4 px -> compress + add length
// ---------------------------------------------------------------------------
__global__ void k_area(int nquad) {
    int t = blockIdx.x * blockDim.x + threadIdx.x;
    if (t >= nquad) return;
    int w = t >> 4;
    int b0 = (t & 15) << 2;
    unsigned long long m = __ldg(&g_bits[w]);
    unsigned long long st = m & ~(m << 1);
    unsigned int s = (unsigned int)((st >> b0) & 0xFull);
    if (!s) return;
    int wbase = w << 5;
    while (s) {
        int k = __ffs(s) - 1;
        s &= s - 1;
        int kk = b0 + k;
        int node = wbase + __popcll(st & ((1ull << kk) - 1ull));
        int root = find_root(node);
        if (root != node) g_lab[node] = root;        // compress
        atomicAdd(&g_ar[root], run_len(m, kk));
    }
}

// ---------------------------------------------------------------------------
// k_bce: PURE STREAMING, no atomics. Thread per 8 px (8 aligned lanes per
// word). Per-run sum of (b-x) assembled via shfl of each lane's leading-
// prefix sum; exactly one plain store per run by its owner lane.
// ---------------------------------------------------------------------------
__global__ void k_bce(const float* __restrict__ in, int nseg8) {
    float fAll = 0.f, fFg = 0.f;
    int t = blockIdx.x * blockDim.x + threadIdx.x;

    // defaults so shfls are uniform even for tail threads
    float head = 0.f;
    float full = 0.f;
    bool active = (t < nseg8);

    int w = t >> 3;
    int j = t & 7;
    int kk0 = j << 3;
    unsigned long long m = 0ull;
    float xs[8];
    unsigned int fgb = 0;

    if (active) {
        const float4* in4 = (const float4*)in;
        int q0 = t * 2;
        m = __ldg(&g_bits[w]);
        float4 v0 = __ldg(&in4[q0]);
        float4 v1 = __ldg(&in4[q0 + 1]);
        xs[0] = v0.x; xs[1] = v0.y; xs[2] = v0.z; xs[3] = v0.w;
        xs[4] = v1.x; xs[5] = v1.y; xs[6] = v1.z; xs[7] = v1.w;
        fgb = (unsigned int)((m >> kk0) & 0xFFull);
    }

    float c[8];
    if (active) {
        float pf = 1.f;
#pragma unroll
        for (int l = 0; l < 8; l++) {
            float x = xs[l];
            float gpl = __logf(1.f + __expf(-fabsf(x)));
            float b = gpl + fmaxf(x, 0.f);
            float sel = (float)((fgb >> l) & 1u);
            fAll += b;
            fFg += sel * b;
            c[l] = sel * (b - x);
            pf *= sel;
            head += pf * c[l];   // wrong: needs prefix BEFORE multiply; fix below
        }
        // recompute head correctly (prefix of consecutive fg from l=0)
        head = 0.f;
        pf = 1.f;
#pragma unroll
        for (int l = 0; l < 8; l++) {
            float sel = (float)((fgb >> l) & 1u);
            pf *= sel;
            head += pf * c[l];
        }
        full = (fgb == 0xFFu && j < 7) ? 1.f : 0.f;
    }

    // shfl exchange (all threads participate)
    float h1 = __shfl_down_sync(0xFFFFFFFFu, head, 1);
    float h2 = __shfl_down_sync(0xFFFFFFFFu, head, 2);
    float h3 = __shfl_down_sync(0xFFFFFFFFu, head, 3);
    float h4 = __shfl_down_sync(0xFFFFFFFFu, head, 4);
    float h5 = __shfl_down_sync(0xFFFFFFFFu, head, 5);
    float h6 = __shfl_down_sync(0xFFFFFFFFu, head, 6);
    float h7 = __shfl_down_sync(0xFFFFFFFFu, head, 7);
    float f1 = __shfl_down_sync(0xFFFFFFFFu, full, 1);
    float f2 = __shfl_down_sync(0xFFFFFFFFu, full, 2);
    float f3 = __shfl_down_sync(0xFFFFFFFFu, full, 3);
    float f4 = __shfl_down_sync(0xFFFFFFFFu, full, 4);
    float f5 = __shfl_down_sync(0xFFFFFFFFu, full, 5);
    float f6 = __shfl_down_sync(0xFFFFFFFFu, full, 6);
    float ext = h1 + f1 * (h2 + f2 * (h3 + f3 * (h4 + f4 * (h5 + f5 * (h6 + f6 * h7)))));

    if (active && fgb) {
        unsigned long long st = m & ~(m << 1);
        unsigned int prev_bit = (kk0 > 0) ? (unsigned int)((m >> (kk0 - 1)) & 1ull) : 0u;
        unsigned int next_bit = (j < 7) ? (unsigned int)((m >> (kk0 + 8)) & 1ull) : 0u;

        float cur = 0.f;
        bool owned = false;
#pragma unroll
        for (int l = 0; l < 8; l++) {
            bool fg = (fgb >> l) & 1u;
            if (fg) {
                bool pfg = (l == 0) ? (prev_bit != 0) : (((fgb >> (l - 1)) & 1u) != 0);
                if (!pfg) { owned = true; cur = 0.f; }
                cur += c[l];
                bool nfg = (l < 7) ? (((fgb >> (l + 1)) & 1u) != 0) : (next_bit != 0);
                if (owned && !nfg) {
                    g_rsum[node_of(w, st, kk0 + l)] = cur;   // run ends here
                    owned = false;
                } else if (owned && l == 7) {
                    g_rsum[node_of(w, st, kk0 + 7)] = cur + ext;  // continues
                    owned = false;
                }
            }
        }
    }

    double d4 = fAll, d5 = fFg;
    __shared__ double sh[2][8];
    int lane = threadIdx.x & 31;
    int warp = threadIdx.x >> 5;
    d4 = warp_sum(d4); d5 = warp_sum(d5);
    if (lane == 0) { sh[0][warp] = d4; sh[1][warp] = d5; }
    __syncthreads();
    if (warp == 0) {
        int nw = blockDim.x >> 5;
        double v4 = (lane < nw) ? sh[0][lane] : 0.0;
        double v5 = (lane < nw) ? sh[1][lane] : 0.0;
        v4 = warp_sum(v4); v5 = warp_sum(v5);
        if (lane == 0) {
            atomicAdd(&g_acc[4], v4);
            atomicAdd(&g_acc[5], v5);
        }
    }
}

// ---------------------------------------------------------------------------
// k_post: 8 threads per word, strided over the word's run slots.
// f0 += rsum/(sqrt(a)+1); roots add a^1.5 (f2) and a (f3).
// ---------------------------------------------------------------------------
__global__ void k_post(int nwords) {
    double d0 = 0.0, d2 = 0.0, d3 = 0.0;
    int t = blockIdx.x * blockDim.x + threadIdx.x;
    int w = t >> 3;
    int j = t & 7;
    if (w < nwords) {
        unsigned long long m = __ldg(&g_bits[w]);
        if (m) {
            unsigned long long st = m & ~(m << 1);
            int ns = __popcll(st);
            int wbase = w << 5;
            float f0 = 0.f, f2 = 0.f, f3 = 0.f;
            for (int r = j; r < ns; r += 8) {
                int nid = wbase + r;
                float rs = __ldg(&g_rsum[nid]);
                int v = __ldg(&g_lab[nid]);
                bool isroot = (v >= nid);           // SENT
                int root = isroot ? nid : v;
                float a = (float)__ldg(&g_ar[root]);
                float sq = sqrtf(a);
                f0 += rs * __fdividef(1.f, sq + 1.f);
                if (isroot) { f2 += a * sq; f3 += a; }
            }
            d0 = f0; d2 = f2; d3 = f3;
        }
    }

    __shared__ double sh[3][8];
    int lane = threadIdx.x & 31;
    int warp = threadIdx.x >> 5;
    d0 = warp_sum(d0); d2 = warp_sum(d2); d3 = warp_sum(d3);
    if (lane == 0) { sh[0][warp] = d0; sh[1][warp] = d2; sh[2][warp] = d3; }
    __syncthreads();
    if (warp == 0) {
        int nw = blockDim.x >> 5;
        double v0 = (lane < nw) ? sh[0][lane] : 0.0;
        double v2 = (lane < nw) ? sh[1][lane] : 0.0;
        double v3 = (lane < nw) ? sh[2][lane] : 0.0;
        v0 = warp_sum(v0); v2 = warp_sum(v2); v3 = warp_sum(v3);
        if (lane == 0) {
            atomicAdd(&g_acc[0], v0);
            atomicAdd(&g_acc[2], v2);
            atomicAdd(&g_acc[3], v3);
        }
    }
}

__global__ void k_final(float* __restrict__ out, double inv_n) {
    double nfg = g_acc[3];
    double mean_nz = g_acc[2] / (nfg > 0.0 ? nfg : 1.0);
    double f1 = g_acc[4] - g_acc[5];   // Σ_bg b = Σ_all b - Σ_fg b
    double loss = (g_acc[0] + f1 / (mean_nz + 1.0)) * inv_n;
    out[0] = (float)loss;
}

// ---------------------------------------------------------------------------
extern "C" void kernel_launch(void* const* d_in, const int* in_sizes, int n_in,
                              void* d_out, int out_size) {
    const float* inputs  = (const float*)d_in[0];
    const float* targets = (const float*)d_in[1];
    float* out = (float*)d_out;

    int n = in_sizes[0];
    int nwords = n >> 6;
    int nquad = n >> 2;
    int nseg8 = n >> 3;
    int nnodes = nwords * 32;
    const int threads = 256;
    int qblocks = (nquad + threads - 1) / threads;
    int wblocks = (nwords + threads - 1) / threads;
    int sblocks = (nseg8 + threads - 1) / threads;
    int pblocks = (nwords * 8 + threads - 1) / threads;

    void *lab_ptr = nullptr, *ar_ptr = nullptr;
    cudaGetSymbolAddress(&lab_ptr, g_lab);
    cudaGetSymbolAddress(&ar_ptr, g_ar);
    cudaMemsetAsync(lab_ptr, 0x7F, (size_t)nnodes * sizeof(int));  // SENT
    cudaMemsetAsync(ar_ptr, 0, (size_t)nnodes * sizeof(int));

    k_prep<<<qblocks, threads>>>(targets, nquad);
    k_union<<<wblocks, threads>>>(nwords);
    k_area<<<qblocks, threads>>>(nquad);
    k_bce<<<sblocks, threads>>>(inputs, nseg8);
    k_post<<<pblocks, threads>>>(nwords);
    k_final<<<1, 1>>>(out, 1.0 / (double)n);
}

// round 14
// speedup vs baseline: 1.1131x; 1.1131x over previous
#include <cuda_runtime.h>
#include <math.h>

#define W_IMG 512
#define H_IMG 512
#define MAX_N (32 * W_IMG * H_IMG)
#define MAX_WORDS (MAX_N / 64)
#define MAX_NODES (MAX_WORDS * 32)   // <=32 runs per 64-px word
#define SENT 0x7F7F7F7F              // "I am root" sentinel (> any node id)

// Run-indexed node arrays (L2-resident).
__device__ int   g_lab[MAX_NODES];   // SENT = root; else parent/root id (< own id)
__device__ int   g_ar[MAX_NODES];    // area at roots
__device__ float g_rsum[MAX_NODES];  // per-run sum of (b - x); plain stores
__device__ unsigned long long g_bits[MAX_WORDS];
// 0 = sum_fg bce/(w+1), 2 = sum_fg w, 3 = N_fg, 4 = sum_all b, 5 = sum_fg b
__device__ double g_acc[6];          // static zeros; k_final re-zeros each call

// ---------------------------------------------------------------------------
__device__ __forceinline__ int find_root(int x) {
    int p = g_lab[x];
    while (p < x) { x = p; p = g_lab[x]; }   // SENT > x  ->  x is root
    return x;
}

__device__ __forceinline__ void merge(int a, int b) {
    while (true) {
        a = find_root(a);
        b = find_root(b);
        if (a == b) return;
        if (a < b) { int t = a; a = b; b = t; }   // a = hi, b = lo
        int old = atomicMin(&g_lab[a], b);
        if (old >= a) return;   // a was root (old==SENT), now linked
        a = old;                // lost race; keep merging previous parent
    }
}

// node id of the run CONTAINING set bit k of word w with starts mask st
__device__ __forceinline__ int node_of(int w, unsigned long long st, int k) {
    return (w << 5) + __popcll(st & ((2ull << k) - 1ull)) - 1;
}

__device__ __forceinline__ int run_len(unsigned long long m, int k) {
    unsigned long long inv = ~(m >> k);
    return inv ? (__ffsll((long long)inv) - 1) : (64 - k);
}

__device__ __forceinline__ double warp_sum(double v) {
#pragma unroll
    for (int off = 16; off > 0; off >>= 1)
        v += __shfl_down_sync(0xFFFFFFFFu, v, off);
    return v;
}

// ---------------------------------------------------------------------------
// k_main: fused prep + streaming bce. Thread per 8 px (8 aligned lanes per
// 64-px word). Builds bits, inits node slots (coalesced int4), computes
// b sums and per-run rsum (one plain store per run via shfl head-exchange).
// ---------------------------------------------------------------------------
__global__ void k_main(const float* __restrict__ in,
                       const float* __restrict__ tgt, int nseg8) {
    float fAll = 0.f, fFg = 0.f;
    int t = blockIdx.x * blockDim.x + threadIdx.x;
    bool active = (t < nseg8);

    int w = t >> 3;
    int j = t & 7;
    int kk0 = j << 3;
    unsigned long long m = 0ull;
    unsigned int fgb = 0;
    float c[8];
    float head = 0.f, full = 0.f;

    if (active) {
        const float4* t4 = (const float4*)tgt;
        const float4* in4 = (const float4*)in;
        int q0 = t * 2;
        // front-batched loads
        float4 a0 = __ldg(&t4[q0]);
        float4 a1 = __ldg(&t4[q0 + 1]);
        float4 v0 = __ldg(&in4[q0]);
        float4 v1 = __ldg(&in4[q0 + 1]);

        // build my 8 mask bits
        unsigned int b8 = 0;
        if (a0.x > 0.f) b8 |= 1u;
        if (a0.y > 0.f) b8 |= 2u;
        if (a0.z > 0.f) b8 |= 4u;
        if (a0.w > 0.f) b8 |= 8u;
        if (a1.x > 0.f) b8 |= 16u;
        if (a1.y > 0.f) b8 |= 32u;
        if (a1.z > 0.f) b8 |= 64u;
        if (a1.w > 0.f) b8 |= 128u;
        fgb = b8;

        // assemble full 64-bit word across the aligned 8-lane group
        unsigned long long mp = ((unsigned long long)b8) << kk0;
        mp |= __shfl_xor_sync(0xFFFFFFFFu, mp, 1);
        mp |= __shfl_xor_sync(0xFFFFFFFFu, mp, 2);
        mp |= __shfl_xor_sync(0xFFFFFFFFu, mp, 4);
        m = mp;
        if (j == 0) g_bits[w] = m;

        // coalesced node-slot init: 8 threads cover the word's 128B lines
        int wbase = w << 5;
        *(int4*)&g_lab[wbase + j * 4] = make_int4(SENT, SENT, SENT, SENT);
        *(int4*)&g_ar[wbase + j * 4] = make_int4(0, 0, 0, 0);

        // per-pixel branchless bce + head (leading fg-prefix sum of c)
        float xs[8] = {v0.x, v0.y, v0.z, v0.w, v1.x, v1.y, v1.z, v1.w};
        float pf = 1.f;
#pragma unroll
        for (int l = 0; l < 8; l++) {
            float x = xs[l];
            float gpl = __logf(1.f + __expf(-fabsf(x)));
            float b = gpl + fmaxf(x, 0.f);     // bce if bg
            float sel = (float)((fgb >> l) & 1u);
            fAll += b;
            fFg += sel * b;
            c[l] = sel * (b - x);              // bce_fg contribution
            pf *= sel;
            head += pf * c[l];
        }
        full = (fgb == 0xFFu && j < 7) ? 1.f : 0.f;
    }

    // shfl head-exchange (all threads participate; cross-group values are
    // guarded by full/next_bit logic and never actually used)
    float h1 = __shfl_down_sync(0xFFFFFFFFu, head, 1);
    float h2 = __shfl_down_sync(0xFFFFFFFFu, head, 2);
    float h3 = __shfl_down_sync(0xFFFFFFFFu, head, 3);
    float h4 = __shfl_down_sync(0xFFFFFFFFu, head, 4);
    float h5 = __shfl_down_sync(0xFFFFFFFFu, head, 5);
    float h6 = __shfl_down_sync(0xFFFFFFFFu, head, 6);
    float h7 = __shfl_down_sync(0xFFFFFFFFu, head, 7);
    float f1 = __shfl_down_sync(0xFFFFFFFFu, full, 1);
    float f2 = __shfl_down_sync(0xFFFFFFFFu, full, 2);
    float f3 = __shfl_down_sync(0xFFFFFFFFu, full, 3);
    float f4 = __shfl_down_sync(0xFFFFFFFFu, full, 4);
    float f5 = __shfl_down_sync(0xFFFFFFFFu, full, 5);
    float f6 = __shfl_down_sync(0xFFFFFFFFu, full, 6);
    float ext = h1 + f1 * (h2 + f2 * (h3 + f3 * (h4 + f4 * (h5 + f5 * (h6 + f6 * h7)))));

    if (active && fgb) {
        unsigned long long st = m & ~(m << 1);
        unsigned int prev_bit = (kk0 > 0) ? (unsigned int)((m >> (kk0 - 1)) & 1ull) : 0u;
        unsigned int next_bit = (j < 7) ? (unsigned int)((m >> (kk0 + 8)) & 1ull) : 0u;

        float cur = 0.f;
        bool owned = false;
#pragma unroll
        for (int l = 0; l < 8; l++) {
            bool fg = (fgb >> l) & 1u;
            if (fg) {
                bool pfg = (l == 0) ? (prev_bit != 0) : (((fgb >> (l - 1)) & 1u) != 0);
                if (!pfg) { owned = true; cur = 0.f; }
                cur += c[l];
                bool nfg = (l < 7) ? (((fgb >> (l + 1)) & 1u) != 0) : (next_bit != 0);
                if (owned && !nfg) {
                    g_rsum[node_of(w, st, kk0 + l)] = cur;        // run ends
                    owned = false;
                } else if (owned && l == 7) {
                    g_rsum[node_of(w, st, kk0 + 7)] = cur + ext;  // continues
                    owned = false;
                }
            }
        }
    }

    double d4 = fAll, d5 = fFg;
    __shared__ double sh[2][8];
    int lane = threadIdx.x & 31;
    int warp = threadIdx.x >> 5;
    d4 = warp_sum(d4); d5 = warp_sum(d5);
    if (lane == 0) { sh[0][warp] = d4; sh[1][warp] = d5; }
    __syncthreads();
    if (warp == 0) {
        int nw = blockDim.x >> 5;
        double v4 = (lane < nw) ? sh[0][lane] : 0.0;
        double v5 = (lane < nw) ? sh[1][lane] : 0.0;
        v4 = warp_sum(v4); v5 = warp_sum(v5);
        if (lane == 0) {
            atomicAdd(&g_acc[4], v4);
            atomicAdd(&g_acc[5], v5);
        }
    }
}

// ---------------------------------------------------------------------------
// k_union: word-level bitmask merges (run-indexed node ids)
// ---------------------------------------------------------------------------
__global__ void k_union(int nwords) {
    int w = blockIdx.x * blockDim.x + threadIdx.x;
    if (w >= nwords) return;
    unsigned long long cur = g_bits[w];
    if (!cur) return;
    unsigned long long stc = cur & ~(cur << 1);
    int wx = w & 7;
    int wy = (w >> 3) & (H_IMG - 1);

    if (wx && (cur & 1ull)) {
        unsigned long long L = g_bits[w - 1];
        if (L >> 63) {
            unsigned long long stl = L & ~(L << 1);
            merge((w << 5), ((w - 1) << 5) + __popcll(stl) - 1);
        }
    }
    if (wy) {
        unsigned long long up = g_bits[w - 8];
        unsigned long long ov = cur & up;
        if (ov) {
            unsigned long long stu = up & ~(up << 1);
            unsigned long long need = ov & ~(ov << 1);
            while (need) {
                int k = __ffsll((long long)need) - 1;
                need &= need - 1;
                merge(node_of(w, stc, k), node_of(w - 8, stu, k));
            }
        }
    }
}

// ---------------------------------------------------------------------------
// k_area: thread per quad; run starts in my 4 px -> compress + add length
// ---------------------------------------------------------------------------
__global__ void k_area(int nquad) {
    int t = blockIdx.x * blockDim.x + threadIdx.x;
    if (t >= nquad) return;
    int w = t >> 4;
    int b0 = (t & 15) << 2;
    unsigned long long m = __ldg(&g_bits[w]);
    unsigned long long st = m & ~(m << 1);
    unsigned int s = (unsigned int)((st >> b0) & 0xFull);
    if (!s) return;
    int wbase = w << 5;
    while (s) {
        int k = __ffs(s) - 1;
        s &= s - 1;
        int kk = b0 + k;
        int node = wbase + __popcll(st & ((1ull << kk) - 1ull));
        int root = find_root(node);
        if (root != node) g_lab[node] = root;        // compress
        atomicAdd(&g_ar[root], run_len(m, kk));
    }
}

// ---------------------------------------------------------------------------
// k_post: 8 threads per word, strided over the word's run slots.
// f0 += rsum/(sqrt(a)+1); roots add a^1.5 (f2) and a (f3).
// ---------------------------------------------------------------------------
__global__ void k_post(int nwords) {
    double d0 = 0.0, d2 = 0.0, d3 = 0.0;
    int t = blockIdx.x * blockDim.x + threadIdx.x;
    int w = t >> 3;
    int j = t & 7;
    if (w < nwords) {
        unsigned long long m = __ldg(&g_bits[w]);
        if (m) {
            unsigned long long st = m & ~(m << 1);
            int ns = __popcll(st);
            int wbase = w << 5;
            float f0 = 0.f, f2 = 0.f, f3 = 0.f;
            for (int r = j; r < ns; r += 8) {
                int nid = wbase + r;
                float rs = __ldg(&g_rsum[nid]);
                int v = __ldg(&g_lab[nid]);
                bool isroot = (v >= nid);            // SENT
                int root = isroot ? nid : v;
                float a = (float)__ldg(&g_ar[root]);
                float sq = sqrtf(a);
                f0 += rs * __fdividef(1.f, sq + 1.f);
                if (isroot) { f2 += a * sq; f3 += a; }
            }
            d0 = f0; d2 = f2; d3 = f3;
        }
    }

    __shared__ double sh[3][8];
    int lane = threadIdx.x & 31;
    int warp = threadIdx.x >> 5;
    d0 = warp_sum(d0); d2 = warp_sum(d2); d3 = warp_sum(d3);
    if (lane == 0) { sh[0][warp] = d0; sh[1][warp] = d2; sh[2][warp] = d3; }
    __syncthreads();
    if (warp == 0) {
        int nw = blockDim.x >> 5;
        double v0 = (lane < nw) ? sh[0][lane] : 0.0;
        double v2 = (lane < nw) ? sh[1][lane] : 0.0;
        double v3 = (lane < nw) ? sh[2][lane] : 0.0;
        v0 = warp_sum(v0); v2 = warp_sum(v2); v3 = warp_sum(v3);
        if (lane == 0) {
            atomicAdd(&g_acc[0], v0);
            atomicAdd(&g_acc[2], v2);
            atomicAdd(&g_acc[3], v3);
        }
    }
}

// ---------------------------------------------------------------------------
// k_final: combine, write output, and RE-ZERO g_acc so the next graph
// replay starts clean (module-load static zeros cover the first call).
// ---------------------------------------------------------------------------
__global__ void k_final(float* __restrict__ out, double inv_n) {
    double nfg = g_acc[3];
    double mean_nz = g_acc[2] / (nfg > 0.0 ? nfg : 1.0);
    double f1 = g_acc[4] - g_acc[5];   // Σ_bg b = Σ_all b - Σ_fg b
    double loss = (g_acc[0] + f1 / (mean_nz + 1.0)) * inv_n;
    out[0] = (float)loss;
#pragma unroll
    for (int i = 0; i < 6; i++) g_acc[i] = 0.0;
}

// ---------------------------------------------------------------------------
extern "C" void kernel_launch(void* const* d_in, const int* in_sizes, int n_in,
                              void* d_out, int out_size) {
    const float* inputs  = (const float*)d_in[0];
    const float* targets = (const float*)d_in[1];
    float* out = (float*)d_out;

    int n = in_sizes[0];
    int nwords = n >> 6;
    int nquad = n >> 2;
    int nseg8 = n >> 3;
    const int threads = 256;
    int sblocks = (nseg8 + threads - 1) / threads;
    int wblocks = (nwords + threads - 1) / threads;
    int qblocks = (nquad + threads - 1) / threads;
    int pblocks = (nwords * 8 + threads - 1) / threads;

    k_main<<<sblocks, threads>>>(inputs, targets, nseg8);
    k_union<<<wblocks, threads>>>(nwords);
    k_area<<<qblocks, threads>>>(nquad);
    k_post<<<pblocks, threads>>>(nwords);
    k_final<<<1, 1>>>(out, 1.0 / (double)n);
}

// round 15
// speedup vs baseline: 1.1233x; 1.0091x over previous
#include <cuda_runtime.h>
#include <math.h>

#define W_IMG 512
#define H_IMG 512
#define MAX_N (32 * W_IMG * H_IMG)
#define MAX_WORDS (MAX_N / 64)
#define MAX_NODES (MAX_WORDS * 32)   // 32 slots per 64-px word
#define SENT 0x7F7F7F7F              // "I am root" sentinel (> any node id)

// Run-indexed node arrays (L2-resident).
__device__ int   g_lab[MAX_NODES];   // SENT = root; else parent/root id (< own id)
__device__ int   g_ar[MAX_NODES];    // area at roots; 0 at non-roots/unused
__device__ float g_rsum[MAX_NODES];  // per-run sum of (b - x); plain stores
__device__ unsigned long long g_bits[MAX_WORDS];
// 0 = sum_fg bce/(w+1), 2 = sum_fg w, 3 = N_fg, 4 = sum_all b, 5 = sum_fg b
__device__ double g_acc[6];          // static zeros; k_final re-zeros each call

// ---------------------------------------------------------------------------
__device__ __forceinline__ int find_root(int x) {
    int p = g_lab[x];
    while (p < x) { x = p; p = g_lab[x]; }   // SENT > x  ->  x is root
    return x;
}

__device__ __forceinline__ void merge(int a, int b) {
    while (true) {
        a = find_root(a);
        b = find_root(b);
        if (a == b) return;
        if (a < b) { int t = a; a = b; b = t; }   // a = hi, b = lo
        int old = atomicMin(&g_lab[a], b);
        if (old >= a) return;   // a was root (old==SENT), now linked
        a = old;                // lost race; keep merging previous parent
    }
}

// node id of the run CONTAINING set bit k of word w with starts mask st
__device__ __forceinline__ int node_of(int w, unsigned long long st, int k) {
    return (w << 5) + __popcll(st & ((2ull << k) - 1ull)) - 1;
}

__device__ __forceinline__ int run_len(unsigned long long m, int k) {
    unsigned long long inv = ~(m >> k);
    return inv ? (__ffsll((long long)inv) - 1) : (64 - k);
}

__device__ __forceinline__ double warp_sum(double v) {
#pragma unroll
    for (int off = 16; off > 0; off >>= 1)
        v += __shfl_down_sync(0xFFFFFFFFu, v, off);
    return v;
}

// ---------------------------------------------------------------------------
// k_main: fused prep + streaming bce. Thread per 8 px (8 aligned lanes per
// 64-px word). Builds bits, inits node slots (coalesced int4), computes
// b sums and per-run rsum (one plain store per run via shfl head-exchange).
// ---------------------------------------------------------------------------
__global__ void k_main(const float* __restrict__ in,
                       const float* __restrict__ tgt, int nseg8) {
    float fAll = 0.f, fFg = 0.f;
    int t = blockIdx.x * blockDim.x + threadIdx.x;
    bool active = (t < nseg8);

    int w = t >> 3;
    int j = t & 7;
    int kk0 = j << 3;
    unsigned long long m = 0ull;
    unsigned int fgb = 0;
    float c[8];
    float head = 0.f, full = 0.f;

    if (active) {
        const float4* t4 = (const float4*)tgt;
        const float4* in4 = (const float4*)in;
        int q0 = t * 2;
        float4 a0 = __ldg(&t4[q0]);
        float4 a1 = __ldg(&t4[q0 + 1]);
        float4 v0 = __ldg(&in4[q0]);
        float4 v1 = __ldg(&in4[q0 + 1]);

        unsigned int b8 = 0;
        if (a0.x > 0.f) b8 |= 1u;
        if (a0.y > 0.f) b8 |= 2u;
        if (a0.z > 0.f) b8 |= 4u;
        if (a0.w > 0.f) b8 |= 8u;
        if (a1.x > 0.f) b8 |= 16u;
        if (a1.y > 0.f) b8 |= 32u;
        if (a1.z > 0.f) b8 |= 64u;
        if (a1.w > 0.f) b8 |= 128u;
        fgb = b8;

        unsigned long long mp = ((unsigned long long)b8) << kk0;
        mp |= __shfl_xor_sync(0xFFFFFFFFu, mp, 1);
        mp |= __shfl_xor_sync(0xFFFFFFFFu, mp, 2);
        mp |= __shfl_xor_sync(0xFFFFFFFFu, mp, 4);
        m = mp;
        if (j == 0) g_bits[w] = m;

        // coalesced node-slot init: 8 threads cover the word's 128B lines
        int wbase = w << 5;
        *(int4*)&g_lab[wbase + j * 4] = make_int4(SENT, SENT, SENT, SENT);
        *(int4*)&g_ar[wbase + j * 4] = make_int4(0, 0, 0, 0);

        float xs[8] = {v0.x, v0.y, v0.z, v0.w, v1.x, v1.y, v1.z, v1.w};
        float pf = 1.f;
#pragma unroll
        for (int l = 0; l < 8; l++) {
            float x = xs[l];
            float gpl = __logf(1.f + __expf(-fabsf(x)));
            float b = gpl + fmaxf(x, 0.f);     // bce if bg
            float sel = (float)((fgb >> l) & 1u);
            fAll += b;
            fFg += sel * b;
            c[l] = sel * (b - x);              // bce_fg contribution
            pf *= sel;
            head += pf * c[l];
        }
        full = (fgb == 0xFFu && j < 7) ? 1.f : 0.f;
    }

    float h1 = __shfl_down_sync(0xFFFFFFFFu, head, 1);
    float h2 = __shfl_down_sync(0xFFFFFFFFu, head, 2);
    float h3 = __shfl_down_sync(0xFFFFFFFFu, head, 3);
    float h4 = __shfl_down_sync(0xFFFFFFFFu, head, 4);
    float h5 = __shfl_down_sync(0xFFFFFFFFu, head, 5);
    float h6 = __shfl_down_sync(0xFFFFFFFFu, head, 6);
    float h7 = __shfl_down_sync(0xFFFFFFFFu, head, 7);
    float f1 = __shfl_down_sync(0xFFFFFFFFu, full, 1);
    float f2 = __shfl_down_sync(0xFFFFFFFFu, full, 2);
    float f3 = __shfl_down_sync(0xFFFFFFFFu, full, 3);
    float f4 = __shfl_down_sync(0xFFFFFFFFu, full, 4);
    float f5 = __shfl_down_sync(0xFFFFFFFFu, full, 5);
    float f6 = __shfl_down_sync(0xFFFFFFFFu, full, 6);
    float ext = h1 + f1 * (h2 + f2 * (h3 + f3 * (h4 + f4 * (h5 + f5 * (h6 + f6 * h7)))));

    if (active && fgb) {
        unsigned long long st = m & ~(m << 1);
        unsigned int prev_bit = (kk0 > 0) ? (unsigned int)((m >> (kk0 - 1)) & 1ull) : 0u;
        unsigned int next_bit = (j < 7) ? (unsigned int)((m >> (kk0 + 8)) & 1ull) : 0u;

        float cur = 0.f;
        bool owned = false;
#pragma unroll
        for (int l = 0; l < 8; l++) {
            bool fg = (fgb >> l) & 1u;
            if (fg) {
                bool pfg = (l == 0) ? (prev_bit != 0) : (((fgb >> (l - 1)) & 1u) != 0);
                if (!pfg) { owned = true; cur = 0.f; }
                cur += c[l];
                bool nfg = (l < 7) ? (((fgb >> (l + 1)) & 1u) != 0) : (next_bit != 0);
                if (owned && !nfg) {
                    g_rsum[node_of(w, st, kk0 + l)] = cur;        // run ends
                    owned = false;
                } else if (owned && l == 7) {
                    g_rsum[node_of(w, st, kk0 + 7)] = cur + ext;  // continues
                    owned = false;
                }
            }
        }
    }

    double d4 = fAll, d5 = fFg;
    __shared__ double sh[2][8];
    int lane = threadIdx.x & 31;
    int warp = threadIdx.x >> 5;
    d4 = warp_sum(d4); d5 = warp_sum(d5);
    if (lane == 0) { sh[0][warp] = d4; sh[1][warp] = d5; }
    __syncthreads();
    if (warp == 0) {
        int nw = blockDim.x >> 5;
        double v4 = (lane < nw) ? sh[0][lane] : 0.0;
        double v5 = (lane < nw) ? sh[1][lane] : 0.0;
        v4 = warp_sum(v4); v5 = warp_sum(v5);
        if (lane == 0) {
            atomicAdd(&g_acc[4], v4);
            atomicAdd(&g_acc[5], v5);
        }
    }
}

// ---------------------------------------------------------------------------
// k_union: word-level bitmask merges (run-indexed node ids)
// ---------------------------------------------------------------------------
__global__ void k_union(int nwords) {
    int w = blockIdx.x * blockDim.x + threadIdx.x;
    if (w >= nwords) return;
    unsigned long long cur = g_bits[w];
    if (!cur) return;
    unsigned long long stc = cur & ~(cur << 1);
    int wx = w & 7;
    int wy = (w >> 3) & (H_IMG - 1);

    if (wx && (cur & 1ull)) {
        unsigned long long L = g_bits[w - 1];
        if (L >> 63) {
            unsigned long long stl = L & ~(L << 1);
            merge((w << 5), ((w - 1) << 5) + __popcll(stl) - 1);
        }
    }
    if (wy) {
        unsigned long long up = g_bits[w - 8];
        unsigned long long ov = cur & up;
        if (ov) {
            unsigned long long stu = up & ~(up << 1);
            unsigned long long need = ov & ~(ov << 1);
            while (need) {
                int k = __ffsll((long long)need) - 1;
                need &= need - 1;
                merge(node_of(w, stc, k), node_of(w - 8, stu, k));
            }
        }
    }
}

// ---------------------------------------------------------------------------
// k_area: thread per quad; run starts in my 4 px -> compress + add length
// ---------------------------------------------------------------------------
__global__ void k_area(int nquad) {
    int t = blockIdx.x * blockDim.x + threadIdx.x;
    if (t >= nquad) return;
    int w = t >> 4;
    int b0 = (t & 15) << 2;
    unsigned long long m = __ldg(&g_bits[w]);
    unsigned long long st = m & ~(m << 1);
    unsigned int s = (unsigned int)((st >> b0) & 0xFull);
    if (!s) return;
    int wbase = w << 5;
    while (s) {
        int k = __ffs(s) - 1;
        s &= s - 1;
        int kk = b0 + k;
        int node = wbase + __popcll(st & ((1ull << kk) - 1ull));
        int root = find_root(node);
        if (root != node) g_lab[node] = root;        // compress
        atomicAdd(&g_ar[root], run_len(m, kk));
    }
}

// ---------------------------------------------------------------------------
// k_post: REGULAR SLOT SWEEP — thread per 4 consecutive node slots.
// Coalesced int4 lab + float4 rsum loads, 4 independent ar[root] gathers.
// used slot <=> ar[root] > 0 (all slots initialized by k_main).
// f0 += rsum/(sqrt(a)+1); roots add a^1.5 (f2) and a (f3).
// ---------------------------------------------------------------------------
__global__ void k_post(int nvec) {
    double d0 = 0.0, d2 = 0.0, d3 = 0.0;
    int t = blockIdx.x * blockDim.x + threadIdx.x;
    if (t < nvec) {
        int4 lb = __ldg(&((const int4*)g_lab)[t]);
        float4 rv = __ldg(&((const float4*)g_rsum)[t]);
        int nid0 = t << 2;
        int labs[4] = {lb.x, lb.y, lb.z, lb.w};
        float rss[4] = {rv.x, rv.y, rv.z, rv.w};

        int root[4];
#pragma unroll
        for (int l = 0; l < 4; l++)
            root[l] = (labs[l] < nid0 + l) ? labs[l] : (nid0 + l);

        float a[4];
#pragma unroll
        for (int l = 0; l < 4; l++)
            a[l] = (float)__ldg(&g_ar[root[l]]);

        float f0 = 0.f, f2 = 0.f, f3 = 0.f;
#pragma unroll
        for (int l = 0; l < 4; l++) {
            float sq = sqrtf(a[l]);
            float contrib = rss[l] * __fdividef(1.f, sq + 1.f);
            f0 += (a[l] > 0.f) ? contrib : 0.f;      // mask unused (garbage rsum)
            bool isroot = labs[l] >= nid0 + l;       // SENT
            f2 += isroot ? a[l] * sq : 0.f;
            f3 += isroot ? a[l] : 0.f;
        }
        d0 = f0; d2 = f2; d3 = f3;
    }

    __shared__ double sh[3][8];
    int lane = threadIdx.x & 31;
    int warp = threadIdx.x >> 5;
    d0 = warp_sum(d0); d2 = warp_sum(d2); d3 = warp_sum(d3);
    if (lane == 0) { sh[0][warp] = d0; sh[1][warp] = d2; sh[2][warp] = d3; }
    __syncthreads();
    if (warp == 0) {
        int nw = blockDim.x >> 5;
        double v0 = (lane < nw) ? sh[0][lane] : 0.0;
        double v2 = (lane < nw) ? sh[1][lane] : 0.0;
        double v3 = (lane < nw) ? sh[2][lane] : 0.0;
        v0 = warp_sum(v0); v2 = warp_sum(v2); v3 = warp_sum(v3);
        if (lane == 0) {
            atomicAdd(&g_acc[0], v0);
            atomicAdd(&g_acc[2], v2);
            atomicAdd(&g_acc[3], v3);
        }
    }
}

// ---------------------------------------------------------------------------
// k_final: combine, write output, and RE-ZERO g_acc so the next graph
// replay starts clean (module-load static zeros cover the first call).
// ---------------------------------------------------------------------------
__global__ void k_final(float* __restrict__ out, double inv_n) {
    double nfg = g_acc[3];
    double mean_nz = g_acc[2] / (nfg > 0.0 ? nfg : 1.0);
    double f1 = g_acc[4] - g_acc[5];   // Σ_bg b = Σ_all b - Σ_fg b
    double loss = (g_acc[0] + f1 / (mean_nz + 1.0)) * inv_n;
    out[0] = (float)loss;
#pragma unroll
    for (int i = 0; i < 6; i++) g_acc[i] = 0.0;
}

// ---------------------------------------------------------------------------
extern "C" void kernel_launch(void* const* d_in, const int* in_sizes, int n_in,
                              void* d_out, int out_size) {
    const float* inputs  = (const float*)d_in[0];
    const float* targets = (const float*)d_in[1];
    float* out = (float*)d_out;

    int n = in_sizes[0];
    int nwords = n >> 6;
    int nquad = n >> 2;
    int nseg8 = n >> 3;
    int nvec = nwords * 8;          // (nwords*32) / 4 slots per thread
    const int threads = 256;
    int sblocks = (nseg8 + threads - 1) / threads;
    int wblocks = (nwords + threads - 1) / threads;
    int qblocks = (nquad + threads - 1) / threads;
    int pblocks = (nvec + threads - 1) / threads;

    k_main<<<sblocks, threads>>>(inputs, targets, nseg8);
    k_union<<<wblocks, threads>>>(nwords);
    k_area<<<qblocks, threads>>>(nquad);
    k_post<<<pblocks, threads>>>(nvec);
    k_final<<<1, 1>>>(out, 1.0 / (double)n);
}